// round 1
// baseline (speedup 1.0000x reference)
#include <cuda_runtime.h>
#include <math.h>

#define TT    1000
#define BB    128
#define NIN   85
#define NRNN  512
#define NOUT  33
#define STEP  (BB * NRNN)   /* 65536 */

// ---------------------------------------------------------------------------
// Scratch (module-load allocated __device__ globals; no runtime allocation)
// ---------------------------------------------------------------------------
__device__ float g_G[(size_t)TT * BB * NRNN];      // pre-gate, 262 MB
__device__ int   g_cnt[NRNN];                      // sparse W_rec: nnz per column
__device__ int   g_idx[NRNN * NRNN];               // row indices  (col-major slabs)
__device__ float g_val[NRNN * NRNN];               // values

// ---------------------------------------------------------------------------
// Kernel 0: build sparse (per-column) representation of W_rec = W[NIN:, :].
// Skipping exact zeros is bit-exact for fp32 accumulation, and for the given
// input (W_rec = 0.5*I) collapses the recurrent GEMM to 1 FMA per element.
// ---------------------------------------------------------------------------
__global__ void prep_sparse(const float* __restrict__ W) {
    int n = threadIdx.x;             // one thread per column, 512 threads
    int c = 0;
    for (int k = 0; k < NRNN; k++) {
        float w = W[(size_t)(NIN + k) * NRNN + n];
        if (w != 0.0f) {
            g_idx[n * NRNN + c] = k;
            g_val[n * NRNN + c] = w;
            c++;
        }
    }
    g_cnt[n] = c;
}

// ---------------------------------------------------------------------------
// Kernel 1: G[m, n] = x[m, :] @ W_in[:, n] + b[n] + noise[m, n]
// M = T*B = 128000, K = 85, N = 512.  64x64 CTA tile, 4x4 per thread.
// ---------------------------------------------------------------------------
__global__ void phase1_kernel(const float* __restrict__ x,
                              const float* __restrict__ W,
                              const float* __restrict__ bias,
                              const float* __restrict__ noise) {
    __shared__ float As[NIN][64];    // x tile, transposed: As[k][row]
    __shared__ float Ws[NIN][64];    // W_in tile: Ws[k][col]

    int tid = threadIdx.x;           // 256 threads
    int m0  = blockIdx.x * 64;       // 2000 blocks
    int n0  = blockIdx.y * 64;       // 8 blocks

    for (int idx = tid; idx < 64 * NIN; idx += 256) {
        int r = idx / NIN;
        int k = idx - r * NIN;
        As[k][r] = x[(size_t)(m0 + r) * NIN + k];
    }
    for (int idx = tid; idx < NIN * 64; idx += 256) {
        int k = idx >> 6;
        int c = idx & 63;
        Ws[k][c] = W[(size_t)k * NRNN + n0 + c];
    }
    __syncthreads();

    int tx = tid & 15;               // col group
    int ty = tid >> 4;               // row group
    float acc[4][4] = {};

    #pragma unroll 5
    for (int k = 0; k < NIN; k++) {
        float4 a = *reinterpret_cast<float4*>(&As[k][ty * 4]);
        float4 w = *reinterpret_cast<float4*>(&Ws[k][tx * 4]);
        float av[4] = {a.x, a.y, a.z, a.w};
        float wv[4] = {w.x, w.y, w.z, w.w};
        #pragma unroll
        for (int i = 0; i < 4; i++)
            #pragma unroll
            for (int j = 0; j < 4; j++)
                acc[i][j] = fmaf(av[i], wv[j], acc[i][j]);
    }

    float4 bb = *reinterpret_cast<const float4*>(&bias[n0 + tx * 4]);
    #pragma unroll
    for (int i = 0; i < 4; i++) {
        int m = m0 + ty * 4 + i;
        size_t off = (size_t)m * NRNN + n0 + tx * 4;
        float4 nz = *reinterpret_cast<const float4*>(&noise[off]);
        float4 o;
        o.x = acc[i][0] + bb.x + nz.x;
        o.y = acc[i][1] + bb.y + nz.y;
        o.z = acc[i][2] + bb.z + nz.z;
        o.w = acc[i][3] + bb.w + nz.w;
        *reinterpret_cast<float4*>(&g_G[off]) = o;
    }
}

// ---------------------------------------------------------------------------
// Kernel 2: sequential recurrence. One CTA per batch element (independent
// chains => no grid sync). h double-buffered in shared, 1 barrier/step,
// G prefetched one step ahead. Sparse recurrent contribution (<=4 nnz in
// registers, generic fallback loop beyond).
// h_t = 0.8*h_{t-1} + 0.2*softplus(G_t + sum_k w[k]*h_{t-1}[k])
// ---------------------------------------------------------------------------
__global__ void recurrence_kernel(float* __restrict__ Hout) {
    __shared__ float hs[2][NRNN];
    int n = threadIdx.x;             // 512 threads: one output column each
    int b = blockIdx.x;              // 128 blocks

    hs[0][n] = 0.0f;

    int cnt = g_cnt[n];
    int   ki[4];
    float wv[4];
    #pragma unroll
    for (int j = 0; j < 4; j++) {
        if (j < cnt) { ki[j] = g_idx[n * NRNN + j]; wv[j] = g_val[n * NRNN + j]; }
        else         { ki[j] = 0;                    wv[j] = 0.0f; }
    }

    const float* Gb = g_G + (size_t)b * NRNN + n;
    float*       Hb = Hout + (size_t)b * NRNN + n;

    __syncthreads();

    int p = 0;
    float gcur = Gb[0];
    for (int t = 0; t < TT; t++) {
        int tn = (t + 1 < TT) ? (t + 1) : t;
        float gnext = Gb[(size_t)tn * STEP];      // prefetch next step's gate

        float acc = gcur;
        acc = fmaf(wv[0], hs[p][ki[0]], acc);
        acc = fmaf(wv[1], hs[p][ki[1]], acc);
        acc = fmaf(wv[2], hs[p][ki[2]], acc);
        acc = fmaf(wv[3], hs[p][ki[3]], acc);
        for (int j = 4; j < cnt; j++)             // generic fallback (unused here)
            acc = fmaf(g_val[n * NRNN + j], hs[p][g_idx[n * NRNN + j]], acc);

        // softplus(x) = max(x,0) + log1p(exp(-|x|))
        float sp = fmaxf(acc, 0.0f) + __logf(1.0f + __expf(-fabsf(acc)));
        float hn = 0.8f * hs[p][n] + 0.2f * sp;

        hs[p ^ 1][n] = hn;
        Hb[(size_t)t * STEP] = hn;
        __syncthreads();
        p ^= 1;
        gcur = gnext;
    }
}

// ---------------------------------------------------------------------------
// Kernel 3: y[m, o] = sigmoid(h[m, :] @ W_out[:, o] + b_out[o])
// M = 128000, K = 512, N = 33. 256 threads, 2 rows/thread, 512 rows/CTA.
// W_out chunk staged in shared (broadcast), 33+33 register accumulators.
// ---------------------------------------------------------------------------
#define P3BK 16
__global__ void phase3_kernel(const float* __restrict__ Hin,
                              const float* __restrict__ Wout,
                              const float* __restrict__ bout,
                              float* __restrict__ y) {
    __shared__ float hsh[512][P3BK + 1];          // +1 pad: conflict-free column reads
    __shared__ float wsh[P3BK][NOUT];

    int tid = threadIdx.x;                        // 256 threads
    int m0  = blockIdx.x * 512;                   // 250 blocks

    float acc0[NOUT] = {};
    float acc1[NOUT] = {};

    for (int k0 = 0; k0 < NRNN; k0 += P3BK) {
        __syncthreads();
        for (int idx = tid; idx < 512 * P3BK; idx += 256) {
            int r = idx >> 4;
            int k = idx & (P3BK - 1);
            hsh[r][k] = Hin[(size_t)(m0 + r) * NRNN + k0 + k];
        }
        for (int idx = tid; idx < P3BK * NOUT; idx += 256) {
            int k = idx / NOUT;
            int o = idx - k * NOUT;
            wsh[k][o] = Wout[(size_t)(k0 + k) * NOUT + o];
        }
        __syncthreads();

        #pragma unroll
        for (int kk = 0; kk < P3BK; kk++) {
            float h0 = hsh[tid][kk];
            float h1 = hsh[tid + 256][kk];
            #pragma unroll
            for (int o = 0; o < NOUT; o++) {
                float w = wsh[kk][o];
                acc0[o] = fmaf(h0, w, acc0[o]);
                acc1[o] = fmaf(h1, w, acc1[o]);
            }
        }
    }

    int r0 = m0 + tid;
    int r1 = m0 + 256 + tid;
    #pragma unroll
    for (int o = 0; o < NOUT; o++) {
        float bo = bout[o];
        float v0 = acc0[o] + bo;
        float v1 = acc1[o] + bo;
        y[(size_t)r0 * NOUT + o] = 1.0f / (1.0f + __expf(-v0));
        y[(size_t)r1 * NOUT + o] = 1.0f / (1.0f + __expf(-v1));
    }
}

// ---------------------------------------------------------------------------
// Launch. Inputs (metadata order): x, W, b, W_out, b_out, noise.
// Output: [y_hat (T*B*33) | h (T*B*512)] fp32, tuple order.
// ---------------------------------------------------------------------------
extern "C" void kernel_launch(void* const* d_in, const int* in_sizes, int n_in,
                              void* d_out, int out_size) {
    const float* x     = (const float*)d_in[0];
    const float* W     = (const float*)d_in[1];
    const float* b     = (const float*)d_in[2];
    const float* W_out = (const float*)d_in[3];
    const float* b_out = (const float*)d_in[4];
    const float* noise = (const float*)d_in[5];

    float* y = (float*)d_out;
    float* h = (float*)d_out + (size_t)TT * BB * NOUT;

    prep_sparse<<<1, NRNN>>>(W);
    phase1_kernel<<<dim3((TT * BB) / 64, NRNN / 64), 256>>>(x, W, b, noise);
    recurrence_kernel<<<BB, NRNN>>>(h);
    phase3_kernel<<<(TT * BB) / 512, 256>>>(h, W_out, b_out, y);
}

// round 2
// speedup vs baseline: 1.5032x; 1.5032x over previous
#include <cuda_runtime.h>
#include <math.h>

#define TT    1000
#define BB    128
#define NIN   85
#define NRNN  512
#define NOUT  33
#define STEP  (BB * NRNN)   /* 65536 */
#define PF    8             /* G prefetch ring depth in diag recurrence */

typedef unsigned long long u64;

// ---------------------------------------------------------------------------
// Packed f32x2 helpers (exact IEEE fp32 per lane; 2x FFMA rate on sm_103a)
// ---------------------------------------------------------------------------
__device__ __forceinline__ u64 pack2(float lo, float hi) {
    u64 r; asm("mov.b64 %0, {%1, %2};" : "=l"(r) : "f"(lo), "f"(hi)); return r;
}
__device__ __forceinline__ void unpack2(u64 v, float& lo, float& hi) {
    asm("mov.b64 {%0, %1}, %2;" : "=f"(lo), "=f"(hi) : "l"(v));
}
__device__ __forceinline__ u64 fma2(u64 a, u64 b, u64 c) {
    u64 d; asm("fma.rn.f32x2 %0, %1, %2, %3;" : "=l"(d) : "l"(a), "l"(b), "l"(c));
    return d;
}

// ---------------------------------------------------------------------------
// Scratch (__device__ globals: module-load allocated, no runtime alloc)
// ---------------------------------------------------------------------------
__device__ float g_G[(size_t)TT * BB * NRNN];      // pre-gate, 262 MB
__device__ int   g_cnt[NRNN];                      // sparse W_rec: nnz per column
__device__ int   g_idx[NRNN * NRNN];               // row indices (col-major slabs)
__device__ float g_val[NRNN * NRNN];               // values
__device__ int   g_diag;                           // 1 iff every column depends only on itself
__device__ float g_wdiag[NRNN];                    // diagonal weight per column

// ---------------------------------------------------------------------------
// Kernel 0: build sparse per-column W_rec; detect pure-diagonal structure.
// Skipping exact zeros is bit-exact for fp32 accumulation.
// ---------------------------------------------------------------------------
__global__ void prep_sparse(const float* __restrict__ W) {
    int n = threadIdx.x;             // 512 threads, one per column
    if (n == 0) g_diag = 1;
    __syncthreads();

    int c = 0;
    for (int k = 0; k < NRNN; k++) {
        float w = W[(size_t)(NIN + k) * NRNN + n];
        if (w != 0.0f) {
            g_idx[n * NRNN + c] = k;
            g_val[n * NRNN + c] = w;
            c++;
        }
    }
    g_cnt[n] = c;
    g_wdiag[n] = (c >= 1) ? g_val[n * NRNN] : 0.0f;

    // diagonal-only iff column n has no deps, or exactly one dep and it's n itself
    int ok = (c == 0) || (c == 1 && g_idx[n * NRNN] == n);
    if (!ok) atomicAnd(&g_diag, 0);
}

// ---------------------------------------------------------------------------
// Kernel 1: G[m,n] = x[m,:] @ W_in[:,n] + b[n] + noise[m,n]
// M=128000, K=85, N=512. 64x64 tile, 4 rows x 4 cols per thread, FFMA2 inner.
// ---------------------------------------------------------------------------
__global__ void phase1_kernel(const float* __restrict__ x,
                              const float* __restrict__ W,
                              const float* __restrict__ bias,
                              const float* __restrict__ noise) {
    __shared__ float As[NIN][64];    // x tile transposed: As[k][row]
    __shared__ u64   Ws2[NIN][32];   // W_in tile, column pairs packed

    int tid = threadIdx.x;           // 256 threads
    int m0  = blockIdx.x * 64;
    int n0  = blockIdx.y * 64;

    for (int idx = tid; idx < 64 * NIN; idx += 256) {
        int r = idx / NIN;
        int k = idx - r * NIN;
        As[k][r] = x[(size_t)(m0 + r) * NIN + k];
    }
    for (int idx = tid; idx < NIN * 32; idx += 256) {
        int k  = idx >> 5;
        int j2 = idx & 31;
        float2 w = *reinterpret_cast<const float2*>(&W[(size_t)k * NRNN + n0 + j2 * 2]);
        Ws2[k][j2] = pack2(w.x, w.y);
    }
    __syncthreads();

    int tx = tid & 15;               // col group (4 cols = 2 packed pairs)
    int ty = tid >> 4;               // row group (4 rows)
    u64 acc[4][2] = {};              // packed (col even, col odd)

    #pragma unroll 5
    for (int k = 0; k < NIN; k++) {
        float4 a = *reinterpret_cast<float4*>(&As[k][ty * 4]);
        ulonglong2 w = *reinterpret_cast<ulonglong2*>(&Ws2[k][tx * 2]);
        u64 ad[4] = { pack2(a.x, a.x), pack2(a.y, a.y),
                      pack2(a.z, a.z), pack2(a.w, a.w) };
        #pragma unroll
        for (int i = 0; i < 4; i++) {
            acc[i][0] = fma2(ad[i], w.x, acc[i][0]);
            acc[i][1] = fma2(ad[i], w.y, acc[i][1]);
        }
    }

    float4 bb = *reinterpret_cast<const float4*>(&bias[n0 + tx * 4]);
    #pragma unroll
    for (int i = 0; i < 4; i++) {
        int m = m0 + ty * 4 + i;
        size_t off = (size_t)m * NRNN + n0 + tx * 4;
        float4 nz = *reinterpret_cast<const float4*>(&noise[off]);
        float a0, a1, a2, a3;
        unpack2(acc[i][0], a0, a1);
        unpack2(acc[i][1], a2, a3);
        float4 o;
        o.x = a0 + bb.x + nz.x;
        o.y = a1 + bb.y + nz.y;
        o.z = a2 + bb.z + nz.z;
        o.w = a3 + bb.w + nz.w;
        *reinterpret_cast<float4*>(&g_G[off]) = o;
    }
}

// ---------------------------------------------------------------------------
// Kernel 2a (fast path): pure-diagonal recurrence. Every (b,n) chain is
// independent: h in a register, no barriers, depth-PF prefetch ring on G.
// h_t = 0.8*h + 0.2*softplus(G_t + w*h)
// ---------------------------------------------------------------------------
__global__ void rec_diag_kernel(float* __restrict__ Hout) {
    if (!g_diag) return;
    int e = blockIdx.x * blockDim.x + threadIdx.x;   // 65536 threads
    int n = e & (NRNN - 1);
    float w = g_wdiag[n];

    const float* Gp = g_G + e;
    float*       Hp = Hout + e;

    float buf[PF];
    #pragma unroll
    for (int i = 0; i < PF; i++) buf[i] = Gp[(size_t)i * STEP];

    float h = 0.0f;
    for (int t0 = 0; t0 < TT; t0 += PF) {
        #pragma unroll
        for (int i = 0; i < PF; i++) {
            int t = t0 + i;
            float g = buf[i];
            int tf = t + PF;
            if (tf < TT) buf[i] = Gp[(size_t)tf * STEP];
            float acc = fmaf(w, h, g);
            float sp  = fmaxf(acc, 0.0f) + __logf(1.0f + __expf(-fabsf(acc)));
            h = 0.8f * h + 0.2f * sp;
            Hp[(size_t)t * STEP] = h;
        }
    }
}

// ---------------------------------------------------------------------------
// Kernel 2b (generic fallback): barriered sparse recurrence, one CTA/batch.
// ---------------------------------------------------------------------------
__global__ void rec_generic_kernel(float* __restrict__ Hout) {
    if (g_diag) return;
    __shared__ float hs[2][NRNN];
    int n = threadIdx.x;
    int b = blockIdx.x;

    hs[0][n] = 0.0f;

    int cnt = g_cnt[n];
    int   ki[4];
    float wv[4];
    #pragma unroll
    for (int j = 0; j < 4; j++) {
        if (j < cnt) { ki[j] = g_idx[n * NRNN + j]; wv[j] = g_val[n * NRNN + j]; }
        else         { ki[j] = 0;                    wv[j] = 0.0f; }
    }

    const float* Gb = g_G + (size_t)b * NRNN + n;
    float*       Hb = Hout + (size_t)b * NRNN + n;
    __syncthreads();

    int p = 0;
    float gcur = Gb[0];
    for (int t = 0; t < TT; t++) {
        int tn = (t + 1 < TT) ? (t + 1) : t;
        float gnext = Gb[(size_t)tn * STEP];

        float acc = gcur;
        acc = fmaf(wv[0], hs[p][ki[0]], acc);
        acc = fmaf(wv[1], hs[p][ki[1]], acc);
        acc = fmaf(wv[2], hs[p][ki[2]], acc);
        acc = fmaf(wv[3], hs[p][ki[3]], acc);
        for (int j = 4; j < cnt; j++)
            acc = fmaf(g_val[n * NRNN + j], hs[p][g_idx[n * NRNN + j]], acc);

        float sp = fmaxf(acc, 0.0f) + __logf(1.0f + __expf(-fabsf(acc)));
        float hn = 0.8f * hs[p][n] + 0.2f * sp;

        hs[p ^ 1][n] = hn;
        Hb[(size_t)t * STEP] = hn;
        __syncthreads();
        p ^= 1;
        gcur = gnext;
    }
}

// ---------------------------------------------------------------------------
// Kernel 3: y[m,o] = sigmoid(h[m,:] @ W_out[:,o] + b_out[o]),  N=33 (pad 34)
// 256 threads, 2 rows/thread, 512 rows/CTA, FFMA2 with packed output pairs.
// ---------------------------------------------------------------------------
#define P3BK 16
#define NO2  17   /* ceil(33/2) packed output pairs */
__global__ void phase3_kernel(const float* __restrict__ Hin,
                              const float* __restrict__ Wout,
                              const float* __restrict__ bout,
                              float* __restrict__ y) {
    __shared__ float hsh[512][P3BK + 1];
    __shared__ u64   wsh2[P3BK][NO2];

    int tid = threadIdx.x;                        // 256 threads
    int m0  = blockIdx.x * 512;                   // 250 blocks

    u64 acc0[NO2] = {};
    u64 acc1[NO2] = {};

    for (int k0 = 0; k0 < NRNN; k0 += P3BK) {
        __syncthreads();
        for (int idx = tid; idx < 512 * P3BK; idx += 256) {
            int r = idx >> 4;
            int k = idx & (P3BK - 1);
            hsh[r][k] = Hin[(size_t)(m0 + r) * NRNN + k0 + k];
        }
        for (int idx = tid; idx < P3BK * NO2; idx += 256) {
            int k  = idx / NO2;
            int o2 = idx - k * NO2;
            float lo = Wout[(size_t)(k0 + k) * NOUT + 2 * o2];
            float hi = (2 * o2 + 1 < NOUT) ? Wout[(size_t)(k0 + k) * NOUT + 2 * o2 + 1] : 0.0f;
            wsh2[k][o2] = pack2(lo, hi);
        }
        __syncthreads();

        #pragma unroll
        for (int kk = 0; kk < P3BK; kk++) {
            u64 hp0 = pack2(hsh[tid][kk],        hsh[tid][kk]);
            u64 hp1 = pack2(hsh[tid + 256][kk],  hsh[tid + 256][kk]);
            #pragma unroll
            for (int o2 = 0; o2 < NO2; o2++) {
                u64 w = wsh2[kk][o2];
                acc0[o2] = fma2(hp0, w, acc0[o2]);
                acc1[o2] = fma2(hp1, w, acc1[o2]);
            }
        }
    }

    int r0 = m0 + tid;
    int r1 = m0 + 256 + tid;
    #pragma unroll
    for (int o2 = 0; o2 < NO2; o2++) {
        float b0 = bout[2 * o2];
        float b1 = (2 * o2 + 1 < NOUT) ? bout[2 * o2 + 1] : 0.0f;
        float v00, v01, v10, v11;
        unpack2(acc0[o2], v00, v01);
        unpack2(acc1[o2], v10, v11);
        y[(size_t)r0 * NOUT + 2 * o2] = 1.0f / (1.0f + __expf(-(v00 + b0)));
        y[(size_t)r1 * NOUT + 2 * o2] = 1.0f / (1.0f + __expf(-(v10 + b0)));
        if (2 * o2 + 1 < NOUT) {
            y[(size_t)r0 * NOUT + 2 * o2 + 1] = 1.0f / (1.0f + __expf(-(v01 + b1)));
            y[(size_t)r1 * NOUT + 2 * o2 + 1] = 1.0f / (1.0f + __expf(-(v11 + b1)));
        }
    }
}

// ---------------------------------------------------------------------------
// Launch. Inputs: x, W, b, W_out, b_out, noise.
// Output: [y_hat (T*B*33) | h (T*B*512)] fp32.
// ---------------------------------------------------------------------------
extern "C" void kernel_launch(void* const* d_in, const int* in_sizes, int n_in,
                              void* d_out, int out_size) {
    const float* x     = (const float*)d_in[0];
    const float* W     = (const float*)d_in[1];
    const float* b     = (const float*)d_in[2];
    const float* W_out = (const float*)d_in[3];
    const float* b_out = (const float*)d_in[4];
    const float* noise = (const float*)d_in[5];

    float* y = (float*)d_out;
    float* h = (float*)d_out + (size_t)TT * BB * NOUT;

    prep_sparse<<<1, NRNN>>>(W);
    phase1_kernel<<<dim3((TT * BB) / 64, NRNN / 64), 256>>>(x, W, b, noise);
    rec_diag_kernel<<<(BB * NRNN) / 256, 256>>>(h);      // fast path (predicated)
    rec_generic_kernel<<<BB, NRNN>>>(h);                 // fallback (predicated)
    phase3_kernel<<<(TT * BB) / 512, 256>>>(h, W_out, b_out, y);
}